// round 8
// baseline (speedup 1.0000x reference)
#include <cuda_runtime.h>
#include <cuda_bf16.h>
#include <math.h>
#include <stdint.h>

#define BINS    10
#define BLOCK   128
#define GRID    592      // 148 SMs * 4 blocks (47KB smem each)
#define NSTAGES 3
#define CHUNK   1024     // elements per array per chunk (4KB)
#define CHUNK_BYTES (CHUNK * 4)

// Per-block partials, bin-major for coalesced last-block reads.
// Written unconditionally every launch -> no zeroing kernel needed.
__device__ float g_psum[BINS * GRID];
__device__ float g_pcnt[BINS * GRID];
__device__ unsigned int g_ticket;   // zero at load; last block resets each launch

__device__ __forceinline__ uint32_t su32(const void* p) {
    return (uint32_t)__cvta_generic_to_shared(p);
}

__device__ __forceinline__ void mbar_init(uint32_t mbar, uint32_t cnt) {
    asm volatile("mbarrier.init.shared.b64 [%0], %1;" :: "r"(mbar), "r"(cnt) : "memory");
}
__device__ __forceinline__ void mbar_expect_tx(uint32_t mbar, uint32_t bytes) {
    asm volatile("mbarrier.arrive.expect_tx.shared.b64 _, [%0], %1;"
                 :: "r"(mbar), "r"(bytes) : "memory");
}
__device__ __forceinline__ void mbar_wait(uint32_t mbar, uint32_t parity) {
    asm volatile(
        "{\n\t.reg .pred P;\n"
        "LW_%=:\n\t"
        "mbarrier.try_wait.parity.acquire.cta.shared::cta.b64 P, [%0], %1, 0x989680;\n\t"
        "@P bra.uni LD_%=;\n\t"
        "bra.uni LW_%=;\n"
        "LD_%=:\n\t}"
        :: "r"(mbar), "r"(parity) : "memory");
}
__device__ __forceinline__ void bulk_copy(uint32_t dst_smem, const void* src, uint32_t bytes,
                                          uint32_t mbar) {
    asm volatile(
        "cp.async.bulk.shared::cluster.global.mbarrier::complete_tx::bytes [%0], [%1], %2, [%3];"
        :: "r"(dst_smem), "l"(src), "r"(bytes), "r"(mbar) : "memory");
}

// ---- R1-verbatim element math (rel_err 5.98e-8) ----
__device__ __forceinline__ void process_elem(float p, float t, float w,
                                             float* s_sum, float* s_cnt, int tid) {
    if (w > 0.0f) {
        float ap = fabsf(p);
        float e  = __expf(-ap);
        float r  = __frcp_rn(1.0f + e);
        float s  = (p >= 0.0f) ? r : e * r;   // sigmoid(p)
        float g  = fabsf(s - t);
        int bin  = (int)(g * 10.0f);
        bin = bin > (BINS - 1) ? (BINS - 1) : bin;
        float bce = fmaxf(p, 0.0f) - p * t + __logf(1.0f + e);
        s_sum[bin * BLOCK + tid] += bce;
        s_cnt[bin * BLOCK + tid] += 1.0f;
    }
}

__global__ void __launch_bounds__(BLOCK)
ghm_main(const float* __restrict__ pred,
         const float* __restrict__ target,
         const float* __restrict__ lw,
         int n, float* __restrict__ out) {
    // Staged input ring: [stage][array][CHUNK] floats = 36KB
    __shared__ alignas(16) float buf[NSTAGES][3][CHUNK];
    // Per-thread private histogram columns: [bin][tid] -> conflict-free.
    __shared__ float s_sum[BINS * BLOCK];
    __shared__ float s_cnt[BINS * BLOCK];
    __shared__ alignas(8) unsigned long long mbar_store[NSTAGES];
    __shared__ bool s_last;

    const int tid = threadIdx.x;
    const int bid = blockIdx.x;

#pragma unroll
    for (int b = 0; b < BINS; b++) {
        s_sum[b * BLOCK + tid] = 0.0f;
        s_cnt[b * BLOCK + tid] = 0.0f;
    }

    uint32_t mbar[NSTAGES];
#pragma unroll
    for (int s = 0; s < NSTAGES; s++) mbar[s] = su32(&mbar_store[s]);
    if (tid == 0) {
#pragma unroll
        for (int s = 0; s < NSTAGES; s++) mbar_init(mbar[s], 1);
    }
    __syncthreads();

    const int nchunks = n / CHUNK;                     // global chunk count
    // Local chunks for this block (grid-stride over chunks): g = bid + i*GRID
    const int nloc = (bid < nchunks) ? (nchunks - bid + GRID - 1) / GRID : 0;

    // Prologue: fill the ring.
    if (tid == 0) {
#pragma unroll
        for (int i = 0; i < NSTAGES; i++) {
            if (i < nloc) {
                long g = (long)bid + (long)i * GRID;
                long off = g * CHUNK;
                mbar_expect_tx(mbar[i], 3 * CHUNK_BYTES);
                bulk_copy(su32(&buf[i][0][0]), pred   + off, CHUNK_BYTES, mbar[i]);
                bulk_copy(su32(&buf[i][1][0]), target + off, CHUNK_BYTES, mbar[i]);
                bulk_copy(su32(&buf[i][2][0]), lw     + off, CHUNK_BYTES, mbar[i]);
            }
        }
    }

    for (int i = 0; i < nloc; i++) {
        const int s   = i % NSTAGES;
        const int par = (i / NSTAGES) & 1;
        mbar_wait(mbar[s], par);

        const float4* pf = (const float4*)&buf[s][0][0];
        const float4* tf = (const float4*)&buf[s][1][0];
        const float4* wf = (const float4*)&buf[s][2][0];
#pragma unroll
        for (int j = 0; j < CHUNK / (4 * BLOCK); j++) {   // 2 iterations
            float4 p = pf[tid + j * BLOCK];
            float4 t = tf[tid + j * BLOCK];
            float4 w = wf[tid + j * BLOCK];
            process_elem(p.x, t.x, w.x, s_sum, s_cnt, tid);
            process_elem(p.y, t.y, w.y, s_sum, s_cnt, tid);
            process_elem(p.z, t.z, w.z, s_sum, s_cnt, tid);
            process_elem(p.w, t.w, w.w, s_sum, s_cnt, tid);
        }
        __syncthreads();   // everyone done reading buf[s] before refill
        if (tid == 0 && i + NSTAGES < nloc) {
            long g = (long)bid + (long)(i + NSTAGES) * GRID;
            long off = g * CHUNK;
            mbar_expect_tx(mbar[s], 3 * CHUNK_BYTES);
            bulk_copy(su32(&buf[s][0][0]), pred   + off, CHUNK_BYTES, mbar[s]);
            bulk_copy(su32(&buf[s][1][0]), target + off, CHUNK_BYTES, mbar[s]);
            bulk_copy(su32(&buf[s][2][0]), lw     + off, CHUNK_BYTES, mbar[s]);
        }
    }

    // Tail (n not multiple of CHUNK) — block 0 direct loads.
    if (bid == 0) {
        for (int j = nchunks * CHUNK + tid; j < n; j += BLOCK)
            process_elem(pred[j], target[j], lw[j], s_sum, s_cnt, tid);
    }

    __syncthreads();
    // Tree-reduce each bin's 128 partials.
    for (int s = BLOCK / 2; s > 0; s >>= 1) {
        if (tid < s) {
#pragma unroll
            for (int b = 0; b < BINS; b++) {
                s_sum[b * BLOCK + tid] += s_sum[b * BLOCK + tid + s];
                s_cnt[b * BLOCK + tid] += s_cnt[b * BLOCK + tid + s];
            }
        }
        __syncthreads();
    }
    if (tid < BINS) {
        g_psum[tid * GRID + bid] = s_sum[tid * BLOCK];
        g_pcnt[tid * GRID + bid] = s_cnt[tid * BLOCK];   // <= 57344, fp32-exact
        __threadfence();    // release, writers only
    }
    __syncthreads();

    // ---- last-block finalization ----
    if (tid == 0) {
        unsigned int t = atomicAdd(&g_ticket, 1u);
        s_last = (t == GRID - 1u);
    }
    __syncthreads();
    if (!s_last) return;

    const int NW = BLOCK / 32;
    double* r_sum = (double*)&buf[0][0][0];          // reuse staged smem
    double* r_cnt = r_sum + BINS * NW;
    const int lane = tid & 31, wid = tid >> 5;

#pragma unroll
    for (int b = 0; b < BINS; b++) {
        float fs = 0.0f, fc = 0.0f;
        const float4* srow = (const float4*)&g_psum[b * GRID];
        const float4* crow = (const float4*)&g_pcnt[b * GRID];
        for (int j = tid; j < GRID / 4; j += BLOCK) {
            float4 vs = __ldcg(&srow[j]);
            float4 vc = __ldcg(&crow[j]);
            fs += (vs.x + vs.y) + (vs.z + vs.w);
            fc += (vc.x + vc.y) + (vc.z + vc.w);     // small exact ints
        }
        double ds = (double)fs, dc = (double)fc;
#pragma unroll
        for (int o = 16; o > 0; o >>= 1) {
            ds += __shfl_down_sync(0xFFFFFFFFu, ds, o);
            dc += __shfl_down_sync(0xFFFFFFFFu, dc, o);
        }
        if (lane == 0) { r_sum[b * NW + wid] = ds; r_cnt[b * NW + wid] = dc; }
    }
    __syncthreads();

    if (tid == 0) {
        double acc = 0.0;
        int ne = 0;
#pragma unroll
        for (int b = 0; b < BINS; b++) {
            double s = 0.0, c = 0.0;
#pragma unroll
            for (int w = 0; w < NW; w++) { s += r_sum[b * NW + w]; c += r_cnt[b * NW + w]; }
            if (c > 0.0) { acc += s / c; ne++; }
        }
        float loss = (ne > 0) ? (float)(acc / (double)ne) : 0.0f;
        out[0] = loss * 1.0f;   // LOSS_WEIGHT
        g_ticket = 0u;          // reset for next graph replay
    }
}

extern "C" void kernel_launch(void* const* d_in, const int* in_sizes, int n_in,
                              void* d_out, int out_size) {
    const float* pred   = (const float*)d_in[0];
    const float* target = (const float*)d_in[1];
    const float* lw     = (const float*)d_in[2];
    float* out = (float*)d_out;
    int n = in_sizes[0];

    ghm_main<<<GRID, BLOCK>>>(pred, target, lw, n, out);
}

// round 9
// speedup vs baseline: 1.3333x; 1.3333x over previous
#include <cuda_runtime.h>
#include <cuda_bf16.h>
#include <math.h>

#define BINS  10
#define BLOCK 256
#define MAXB  5          // blocks/SM -> 51-reg budget, 40 warps/SM
#define GRID  (148 * MAXB)   // 740, fully resident in one wave

// Per-block partials, bin-major for coalesced last-block reads.
// Written unconditionally by every block every launch -> no zeroing needed.
__device__ float g_psum[BINS * GRID];
__device__ float g_pcnt[BINS * GRID];
__device__ unsigned int g_ticket;   // zero-init at load; last block resets each launch

// ---- R1-verbatim element math (rel_err 5.98e-8) ----
__device__ __forceinline__ void process_elem(float p, float t, float w,
                                             float* s_sum, float* s_cnt, int tid) {
    if (w > 0.0f) {
        float ap = fabsf(p);
        float e  = __expf(-ap);          // exp(-|p|)
        float r  = __frcp_rn(1.0f + e);  // 1/(1+e)
        float s  = (p >= 0.0f) ? r : e * r;   // sigmoid(p)
        float g  = fabsf(s - t);
        int bin  = (int)(g * 10.0f);
        bin = bin > (BINS - 1) ? (BINS - 1) : bin;
        float bce = fmaxf(p, 0.0f) - p * t + __logf(1.0f + e);
        s_sum[bin * BLOCK + tid] += bce;
        s_cnt[bin * BLOCK + tid] += 1.0f;
    }
}

__global__ void __launch_bounds__(BLOCK, MAXB)
ghm_main(const float* __restrict__ pred,
         const float* __restrict__ target,
         const float* __restrict__ lw,
         int n, float* __restrict__ out) {
    // Per-thread private histogram columns: [bin][tid] -> bank = tid%32, conflict-free.
    __shared__ float s_sum[BINS * BLOCK];
    __shared__ float s_cnt[BINS * BLOCK];

    const int tid = threadIdx.x;
#pragma unroll
    for (int b = 0; b < BINS; b++) {
        s_sum[b * BLOCK + tid] = 0.0f;
        s_cnt[b * BLOCK + tid] = 0.0f;
    }

    const int n4 = n >> 2;
    const float4* __restrict__ p4 = (const float4*)pred;
    const float4* __restrict__ t4 = (const float4*)target;
    const float4* __restrict__ w4 = (const float4*)lw;

    const int stride = GRID * BLOCK;
    int i = blockIdx.x * BLOCK + tid;

    if (i < n4) {
        // Register software pipeline. With the 51-reg budget (MAXB=5) ptxas can
        // keep both triples live, so next-iter LDG.128s issue before this
        // iter's compute -> ~6 loads in flight per warp, latency covered.
        float4 pa = p4[i];
        float4 ta = t4[i];
        float4 wa = w4[i];
        int inext = i + stride;
        while (inext < n4) {
            float4 pb = p4[inext];
            float4 tb = t4[inext];
            float4 wb = w4[inext];
            process_elem(pa.x, ta.x, wa.x, s_sum, s_cnt, tid);
            process_elem(pa.y, ta.y, wa.y, s_sum, s_cnt, tid);
            process_elem(pa.z, ta.z, wa.z, s_sum, s_cnt, tid);
            process_elem(pa.w, ta.w, wa.w, s_sum, s_cnt, tid);
            pa = pb; ta = tb; wa = wb;
            inext += stride;
        }
        process_elem(pa.x, ta.x, wa.x, s_sum, s_cnt, tid);
        process_elem(pa.y, ta.y, wa.y, s_sum, s_cnt, tid);
        process_elem(pa.z, ta.z, wa.z, s_sum, s_cnt, tid);
        process_elem(pa.w, ta.w, wa.w, s_sum, s_cnt, tid);
    }
    // Scalar tail (n not multiple of 4) — block 0 only.
    if (blockIdx.x == 0) {
        for (int j = (n4 << 2) + tid; j < n; j += BLOCK)
            process_elem(pred[j], target[j], lw[j], s_sum, s_cnt, tid);
    }

    __syncthreads();
    // Tree-reduce each bin's 256 partials.
    for (int s = BLOCK / 2; s > 0; s >>= 1) {
        if (tid < s) {
#pragma unroll
            for (int b = 0; b < BINS; b++) {
                s_sum[b * BLOCK + tid] += s_sum[b * BLOCK + tid + s];
                s_cnt[b * BLOCK + tid] += s_cnt[b * BLOCK + tid + s];
            }
        }
        __syncthreads();
    }
    if (tid < BINS) {
        g_psum[tid * GRID + blockIdx.x] = s_sum[tid * BLOCK];
        g_pcnt[tid * GRID + blockIdx.x] = s_cnt[tid * BLOCK];  // fp32-exact (<2^18)
        __threadfence();   // release, writers only
    }
    __syncthreads();

    // ---- last-block finalization (no extra kernel launches) ----
    __shared__ bool s_last;
    if (tid == 0) {
        unsigned int t = atomicAdd(&g_ticket, 1u);
        s_last = (t == GRID - 1u);
    }
    __syncthreads();
    if (!s_last) return;

    __shared__ double r_sum[BINS * (BLOCK / 32)];
    __shared__ double r_cnt[BINS * (BLOCK / 32)];
    const int lane = tid & 31, wid = tid >> 5;
    const int NW = BLOCK / 32;

#pragma unroll
    for (int b = 0; b < BINS; b++) {
        float fs = 0.0f, fc = 0.0f;
        const float4* srow = (const float4*)&g_psum[b * GRID];
        const float4* crow = (const float4*)&g_pcnt[b * GRID];
        for (int j = tid; j < GRID / 4; j += BLOCK) {
            float4 vs = __ldcg(&srow[j]);   // coalesced, bypass stale L1
            float4 vc = __ldcg(&crow[j]);
            fs += (vs.x + vs.y) + (vs.z + vs.w);
            fc += (vc.x + vc.y) + (vc.z + vc.w);  // sums of small exact ints
        }
        double ds = (double)fs, dc = (double)fc;
#pragma unroll
        for (int o = 16; o > 0; o >>= 1) {
            ds += __shfl_down_sync(0xFFFFFFFFu, ds, o);
            dc += __shfl_down_sync(0xFFFFFFFFu, dc, o);
        }
        if (lane == 0) { r_sum[b * NW + wid] = ds; r_cnt[b * NW + wid] = dc; }
    }
    __syncthreads();

    if (tid == 0) {
        double acc = 0.0;
        int ne = 0;
#pragma unroll
        for (int b = 0; b < BINS; b++) {
            double s = 0.0, c = 0.0;
#pragma unroll
            for (int w = 0; w < NW; w++) { s += r_sum[b * NW + w]; c += r_cnt[b * NW + w]; }
            if (c > 0.0) { acc += s / c; ne++; }
        }
        float loss = (ne > 0) ? (float)(acc / (double)ne) : 0.0f;
        out[0] = loss * 1.0f;   // LOSS_WEIGHT
        g_ticket = 0u;          // reset for next graph replay
    }
}

extern "C" void kernel_launch(void* const* d_in, const int* in_sizes, int n_in,
                              void* d_out, int out_size) {
    const float* pred   = (const float*)d_in[0];
    const float* target = (const float*)d_in[1];
    const float* lw     = (const float*)d_in[2];
    float* out = (float*)d_out;
    int n = in_sizes[0];

    ghm_main<<<GRID, BLOCK>>>(pred, target, lw, n, out);
}